// round 1
// baseline (speedup 1.0000x reference)
#include <cuda_runtime.h>
#include <cuda_bf16.h>

// PyramidROIAlign: output [B,N,7,7,256] f32, levels p2..p5 (256/128/64/32), NHWC.
// One thread per float4 of channels. idx = ((roi*49)+pos)*64 + c4 maps 1:1 to the
// output float4 stream -> fully coalesced stores; gathers coalesced over channels.

#define POOLX 7
#define C_CH 256
#define C4N (C_CH / 4)   // 64 float4 per (roi,py,px)

__global__ __launch_bounds__(256) void roi_align_kernel(
    const float* __restrict__ boxes,   // [M,4]  (y1,x1,y2,x2)
    const float* __restrict__ meta,    // [B,93]
    const float* __restrict__ p2,
    const float* __restrict__ p3,
    const float* __restrict__ p4,
    const float* __restrict__ p5,
    float* __restrict__ out,
    int total4, int N)
{
    int idx = blockIdx.x * blockDim.x + threadIdx.x;
    if (idx >= total4) return;

    int c4  = idx & (C4N - 1);
    int t   = idx >> 6;          // roi*49 + pos
    int pos = t % 49;
    int roi = t / 49;
    int b   = roi / N;
    int py  = pos / POOLX;
    int px  = pos - py * POOLX;

    // Box (uniform within warp -> single L1 transaction)
    float4 bx = __ldg(((const float4*)boxes) + roi);
    float y1 = bx.x, x1 = bx.y, y2 = bx.z, x2 = bx.w;
    float h = y2 - y1, w = x2 - x1;

    // Level selection (matches: lvl = clip(4 + round(log2(scale*sqrt(area)/224)), 2, 5))
    float area  = __ldg(meta + 4) * __ldg(meta + 5);
    float scale = sqrtf(fmaxf(h * w, 1e-12f));
    float rl    = log2f(scale * sqrtf(area) / 224.0f);
    int lvl = 4 + (int)rintf(rl);         // rintf = round-half-even, matches jnp.round
    lvl = min(max(lvl, 2), 5);

    const float* fmap;
    int H;
    if      (lvl == 2) { fmap = p2; H = 256; }
    else if (lvl == 3) { fmap = p3; H = 128; }
    else if (lvl == 4) { fmap = p4; H = 64;  }
    else               { fmap = p5; H = 32;  }
    const int W = H;

    // Sample coordinates (match reference op order)
    float ty = (float)py / 6.0f;
    float tx = (float)px / 6.0f;
    float ys = (y1 + ty * h) * (float)(H - 1);
    float xs = (x1 + tx * w) * (float)(W - 1);

    float fy = floorf(ys), fx = floorf(xs);
    float ly = ys - fy,    lx = xs - fx;

    int y0  = min(max((int)fy,     0), H - 1);
    int y1i = min(max((int)fy + 1, 0), H - 1);
    int x0  = min(max((int)fx,     0), W - 1);
    int x1i = min(max((int)fx + 1, 0), W - 1);

    const float4* f4 = (const float4*)fmap;
    int rowT = (b * H + y0)  * W;   // "top" row (y0)
    int rowB = (b * H + y1i) * W;   // "bottom" row (y1)

    float4 v00 = __ldg(f4 + (rowT + x0 ) * C4N + c4);
    float4 v01 = __ldg(f4 + (rowT + x1i) * C4N + c4);
    float4 v10 = __ldg(f4 + (rowB + x0 ) * C4N + c4);
    float4 v11 = __ldg(f4 + (rowB + x1i) * C4N + c4);

    float omlx = 1.0f - lx;
    float omly = 1.0f - ly;

    float4 r;
    {
        float top = v00.x * omlx + v01.x * lx;
        float bot = v10.x * omlx + v11.x * lx;
        r.x = top * omly + bot * ly;
    }
    {
        float top = v00.y * omlx + v01.y * lx;
        float bot = v10.y * omlx + v11.y * lx;
        r.y = top * omly + bot * ly;
    }
    {
        float top = v00.z * omlx + v01.z * lx;
        float bot = v10.z * omlx + v11.z * lx;
        r.z = top * omly + bot * ly;
    }
    {
        float top = v00.w * omlx + v01.w * lx;
        float bot = v10.w * omlx + v11.w * lx;
        r.w = top * omly + bot * ly;
    }

    ((float4*)out)[idx] = r;
}

extern "C" void kernel_launch(void* const* d_in, const int* in_sizes, int n_in,
                              void* d_out, int out_size) {
    const float* boxes = (const float*)d_in[0];
    const float* meta  = (const float*)d_in[1];
    const float* p2    = (const float*)d_in[2];
    const float* p3    = (const float*)d_in[3];
    const float* p4    = (const float*)d_in[4];
    const float* p5    = (const float*)d_in[5];
    float* out = (float*)d_out;

    int B = in_sizes[1] / 93;              // image_meta [B,93]
    if (B <= 0) B = 2;
    int N = in_sizes[0] / (4 * B);         // boxes [B,N,4]
    int total4 = out_size / 4;             // float4 output elements

    int threads = 256;
    int blocks  = (total4 + threads - 1) / threads;
    roi_align_kernel<<<blocks, threads>>>(boxes, meta, p2, p3, p4, p5, out, total4, N);
}

// round 2
// speedup vs baseline: 1.3309x; 1.3309x over previous
#include <cuda_runtime.h>
#include <cuda_bf16.h>

// PyramidROIAlign: output [B,N,7,7,256] f32, levels p2..p5 (256/128/64/32), NHWC.
// One WARP per (roi, py, px) sample; each lane handles 2 float4s of channels
// (lane, lane+32). All per-sample setup (level select, bilinear coords/weights,
// addresses) is computed once per warp; lanes do only vector loads + FFMA + store.

#define POOLX 7
#define C4N 64   // 256 ch / 4

__global__ __launch_bounds__(256) void roi_align_warp_kernel(
    const float* __restrict__ boxes,   // [M,4]  (y1,x1,y2,x2)
    const float* __restrict__ meta,    // [B,93]
    const float* __restrict__ p2,
    const float* __restrict__ p3,
    const float* __restrict__ p4,
    const float* __restrict__ p5,
    float* __restrict__ out,
    int totalWarps, int N)
{
    int gw   = (blockIdx.x * blockDim.x + threadIdx.x) >> 5;  // warp id = sample id
    int lane = threadIdx.x & 31;
    if (gw >= totalWarps) return;

    int pos = gw % 49;
    int roi = gw / 49;
    int b   = roi / N;
    int py  = pos / POOLX;
    int px  = pos - py * POOLX;

    // ---- per-warp uniform setup ----
    float4 bx = __ldg(((const float4*)boxes) + roi);
    float y1 = bx.x, x1 = bx.y, y2 = bx.z, x2 = bx.w;
    float h = y2 - y1, w = x2 - x1;

    float area  = __ldg(meta + 4) * __ldg(meta + 5);
    float scale = sqrtf(fmaxf(h * w, 1e-12f));
    float rl    = log2f(scale * sqrtf(area) / 224.0f);
    int lvl = 4 + (int)rintf(rl);
    lvl = min(max(lvl, 2), 5);

    const float* fmap;
    int H;
    if      (lvl == 2) { fmap = p2; H = 256; }
    else if (lvl == 3) { fmap = p3; H = 128; }
    else if (lvl == 4) { fmap = p4; H = 64;  }
    else               { fmap = p5; H = 32;  }
    const int W = H;

    float ty = (float)py * (1.0f / 6.0f);
    float tx = (float)px * (1.0f / 6.0f);
    float ys = (y1 + ty * h) * (float)(H - 1);
    float xs = (x1 + tx * w) * (float)(W - 1);

    float fy = floorf(ys), fx = floorf(xs);
    float ly = ys - fy,    lx = xs - fx;

    int y0  = min(max((int)fy,     0), H - 1);
    int y1i = min(max((int)fy + 1, 0), H - 1);
    int x0  = min(max((int)fx,     0), W - 1);
    int x1i = min(max((int)fx + 1, 0), W - 1);

    float w01 = lx - ly * lx;          // lx*(1-ly)
    float w11 = ly * lx;
    float w10 = ly - w11;              // ly*(1-lx)
    float w00 = 1.0f - lx - w10;       // (1-lx)*(1-ly)

    const float4* f4 = (const float4*)fmap;
    long base00 = (long)((b * H + y0 ) * W + x0 ) * C4N;
    long base01 = (long)((b * H + y0 ) * W + x1i) * C4N;
    long base10 = (long)((b * H + y1i) * W + x0 ) * C4N;
    long base11 = (long)((b * H + y1i) * W + x1i) * C4N;

    // ---- per-lane hot path: 8 x LDG.128, FFMAs, 2 x STG.128 ----
    int cA = lane, cB = lane + 32;

    float4 a00 = __ldg(f4 + base00 + cA);
    float4 a01 = __ldg(f4 + base01 + cA);
    float4 a10 = __ldg(f4 + base10 + cA);
    float4 a11 = __ldg(f4 + base11 + cA);
    float4 b00 = __ldg(f4 + base00 + cB);
    float4 b01 = __ldg(f4 + base01 + cB);
    float4 b10 = __ldg(f4 + base10 + cB);
    float4 b11 = __ldg(f4 + base11 + cB);

    float4 ra, rb;
    ra.x = a00.x*w00 + a01.x*w01 + a10.x*w10 + a11.x*w11;
    ra.y = a00.y*w00 + a01.y*w01 + a10.y*w10 + a11.y*w11;
    ra.z = a00.z*w00 + a01.z*w01 + a10.z*w10 + a11.z*w11;
    ra.w = a00.w*w00 + a01.w*w01 + a10.w*w10 + a11.w*w11;
    rb.x = b00.x*w00 + b01.x*w01 + b10.x*w10 + b11.x*w11;
    rb.y = b00.y*w00 + b01.y*w01 + b10.y*w10 + b11.y*w11;
    rb.z = b00.z*w00 + b01.z*w01 + b10.z*w10 + b11.z*w11;
    rb.w = b00.w*w00 + b01.w*w01 + b10.w*w10 + b11.w*w11;

    float4* o4 = (float4*)out + (long)gw * C4N;
    o4[cA] = ra;
    o4[cB] = rb;
}

extern "C" void kernel_launch(void* const* d_in, const int* in_sizes, int n_in,
                              void* d_out, int out_size) {
    const float* boxes = (const float*)d_in[0];
    const float* meta  = (const float*)d_in[1];
    const float* p2    = (const float*)d_in[2];
    const float* p3    = (const float*)d_in[3];
    const float* p4    = (const float*)d_in[4];
    const float* p5    = (const float*)d_in[5];
    float* out = (float*)d_out;

    int B = in_sizes[1] / 93;              // image_meta [B,93]
    if (B <= 0) B = 2;
    int N = in_sizes[0] / (4 * B);         // boxes [B,N,4]
    int M = B * N;
    int totalWarps = M * 49;               // one warp per (roi, py, px)

    int threads = 256;                      // 8 warps per block
    int warpsPerBlock = threads / 32;
    int blocks = (totalWarps + warpsPerBlock - 1) / warpsPerBlock;
    roi_align_warp_kernel<<<blocks, threads>>>(boxes, meta, p2, p3, p4, p5, out,
                                               totalWarps, N);
}

// round 3
// speedup vs baseline: 1.5825x; 1.1891x over previous
#include <cuda_runtime.h>
#include <cuda_bf16.h>

// PyramidROIAlign: output [B,N,7,7,256] f32, levels p2..p5 (256/128/64/32), NHWC.
// One WARP per (roi, py, px) sample; each lane handles 2 float4s of channels.
// R3: 32-bit addressing (register diet, launch_bounds min-blocks=8 for occupancy),
// __stcs streaming stores so the 100MB output doesn't evict the gather working
// set from L2.

#define POOLX 7
#define C4N 64   // 256 ch / 4

__global__ __launch_bounds__(256, 8) void roi_align_warp_kernel(
    const float* __restrict__ boxes,   // [M,4]  (y1,x1,y2,x2)
    const float* __restrict__ meta,    // [B,93]
    const float* __restrict__ p2,
    const float* __restrict__ p3,
    const float* __restrict__ p4,
    const float* __restrict__ p5,
    float* __restrict__ out,
    int totalWarps, int N)
{
    int gw   = (blockIdx.x * blockDim.x + threadIdx.x) >> 5;  // warp id = sample id
    int lane = threadIdx.x & 31;
    if (gw >= totalWarps) return;

    int pos = gw % 49;
    int roi = gw / 49;
    int b   = roi / N;
    int py  = pos / POOLX;
    int px  = pos - py * POOLX;

    // ---- per-warp uniform setup ----
    float4 bx = __ldg(((const float4*)boxes) + roi);
    float y1 = bx.x, x1 = bx.y, y2 = bx.z, x2 = bx.w;
    float h = y2 - y1, w = x2 - x1;

    float area  = __ldg(meta + 4) * __ldg(meta + 5);
    float scale = sqrtf(fmaxf(h * w, 1e-12f));
    float rl    = log2f(scale * sqrtf(area) / 224.0f);
    int lvl = 4 + (int)rintf(rl);
    lvl = min(max(lvl, 2), 5);

    const float* fmap;
    int H;
    if      (lvl == 2) { fmap = p2; H = 256; }
    else if (lvl == 3) { fmap = p3; H = 128; }
    else if (lvl == 4) { fmap = p4; H = 64;  }
    else               { fmap = p5; H = 32;  }
    const int W = H;

    float ty = (float)py * (1.0f / 6.0f);
    float tx = (float)px * (1.0f / 6.0f);
    float ys = (y1 + ty * h) * (float)(H - 1);
    float xs = (x1 + tx * w) * (float)(W - 1);

    float fy = floorf(ys), fx = floorf(xs);
    float ly = ys - fy,    lx = xs - fx;

    int y0  = min(max((int)fy,     0), H - 1);
    int y1i = min(max((int)fy + 1, 0), H - 1);
    int x0  = min(max((int)fx,     0), W - 1);
    int x1i = min(max((int)fx + 1, 0), W - 1);

    float w01 = lx - ly * lx;          // lx*(1-ly)
    float w11 = ly * lx;
    float w10 = ly - w11;              // ly*(1-lx)
    float w00 = 1.0f - lx - w10;       // (1-lx)*(1-ly)

    // 32-bit float4-element offsets (max 2*256*256*64 = 8.4M, fits easily)
    const float4* f4 = (const float4*)fmap;
    int rowT = (b * H + y0 ) * W;
    int rowB = (b * H + y1i) * W;
    int cA = lane, cB = lane + 32;
    int o00 = (rowT + x0 ) * C4N + cA;
    int o01 = (rowT + x1i) * C4N + cA;
    int o10 = (rowB + x0 ) * C4N + cA;
    int o11 = (rowB + x1i) * C4N + cA;

    // ---- per-lane hot path: 8 x LDG.128 (all issued up front), FFMAs, 2 x STG ----
    float4 a00 = __ldg(f4 + o00);
    float4 a01 = __ldg(f4 + o01);
    float4 a10 = __ldg(f4 + o10);
    float4 a11 = __ldg(f4 + o11);
    float4 b00 = __ldg(f4 + o00 + 32);
    float4 b01 = __ldg(f4 + o01 + 32);
    float4 b10 = __ldg(f4 + o10 + 32);
    float4 b11 = __ldg(f4 + o11 + 32);

    float4 ra, rb;
    ra.x = a00.x*w00 + a01.x*w01 + a10.x*w10 + a11.x*w11;
    ra.y = a00.y*w00 + a01.y*w01 + a10.y*w10 + a11.y*w11;
    ra.z = a00.z*w00 + a01.z*w01 + a10.z*w10 + a11.z*w11;
    ra.w = a00.w*w00 + a01.w*w01 + a10.w*w10 + a11.w*w11;
    rb.x = b00.x*w00 + b01.x*w01 + b10.x*w10 + b11.x*w11;
    rb.y = b00.y*w00 + b01.y*w01 + b10.y*w10 + b11.y*w11;
    rb.z = b00.z*w00 + b01.z*w01 + b10.z*w10 + b11.z*w11;
    rb.w = b00.w*w00 + b01.w*w01 + b10.w*w10 + b11.w*w11;

    // Streaming (evict-first) stores: keep the output out of L2's way.
    float4* o4 = (float4*)out + gw * C4N;
    __stcs(o4 + cA, ra);
    __stcs(o4 + cB, rb);
}

extern "C" void kernel_launch(void* const* d_in, const int* in_sizes, int n_in,
                              void* d_out, int out_size) {
    const float* boxes = (const float*)d_in[0];
    const float* meta  = (const float*)d_in[1];
    const float* p2    = (const float*)d_in[2];
    const float* p3    = (const float*)d_in[3];
    const float* p4    = (const float*)d_in[4];
    const float* p5    = (const float*)d_in[5];
    float* out = (float*)d_out;

    int B = in_sizes[1] / 93;              // image_meta [B,93]
    if (B <= 0) B = 2;
    int N = in_sizes[0] / (4 * B);         // boxes [B,N,4]
    int M = B * N;
    int totalWarps = M * 49;               // one warp per (roi, py, px)

    int threads = 256;                      // 8 warps per block
    int warpsPerBlock = threads / 32;
    int blocks = (totalWarps + warpsPerBlock - 1) / warpsPerBlock;
    roi_align_warp_kernel<<<blocks, threads>>>(boxes, meta, p2, p3, p4, p5, out,
                                               totalWarps, N);
}